// round 9
// baseline (speedup 1.0000x reference)
#include <cuda_runtime.h>
#include <cuda_fp16.h>

#define NN 50000
#define NE 800000
#define ET (NE + NN)
#define SLOPE 0.2f
#define BUCKET 64        // padded CSR stride; deg ~ Poisson(16)+1, P(deg>63) ~ e^-30

// ---------------- scratch (static device globals; no allocation) ----------------
__device__ __half g_h1h[NN * 128];   // layer1 projected features (fp16)
__device__ float  g_e1s[NN * 4];
__device__ float  g_e1d[NN * 4];
__device__ __half g_h2h[NN * 64];    // layer2 projected (fp16)
__device__ float  g_e2s[NN];
__device__ float  g_e2d[NN];
__device__ float  g_wal[128];        // W2 @ a2_l  (for e2 logits)
__device__ float  g_war[128];        // W2 @ a2_r
__device__ int    g_deg[NN];         // atomic cursors == final degrees
__device__ int    g_row2[NN * BUCKET]; // padded adjacency (by dst): source node per slot
__device__ int    g_is64;

// ---------------- small helpers ----------------
__device__ __forceinline__ unsigned long long pack2(float lo, float hi) {
    unsigned long long r;
    asm("mov.b64 %0, {%1, %2};" : "=l"(r) : "f"(lo), "f"(hi));
    return r;
}
__device__ __forceinline__ void fma2(unsigned long long& d, unsigned long long a, unsigned long long b) {
    asm("fma.rn.f32x2 %0, %1, %2, %0;" : "+l"(d) : "l"(a), "l"(b));
}
__device__ __forceinline__ float lrelu(float a) { return a > 0.f ? a : SLOPE * a; }

__device__ __forceinline__ unsigned smaddr(const void* p) {
    return (unsigned)__cvta_generic_to_shared(p);
}
__device__ __forceinline__ void ldsm_x4(unsigned& r0, unsigned& r1, unsigned& r2, unsigned& r3, unsigned a) {
    asm volatile("ldmatrix.sync.aligned.m8n8.x4.shared.b16 {%0,%1,%2,%3}, [%4];"
                 : "=r"(r0), "=r"(r1), "=r"(r2), "=r"(r3) : "r"(a));
}
__device__ __forceinline__ void ldsm_x4_t(unsigned& r0, unsigned& r1, unsigned& r2, unsigned& r3, unsigned a) {
    asm volatile("ldmatrix.sync.aligned.m8n8.x4.trans.shared.b16 {%0,%1,%2,%3}, [%4];"
                 : "=r"(r0), "=r"(r1), "=r"(r2), "=r"(r3) : "r"(a));
}
__device__ __forceinline__ void mma16816(float* c, const unsigned* a, const unsigned* b) {
    asm volatile("mma.sync.aligned.m16n8k16.row.col.f32.f16.f16.f32 "
                 "{%0,%1,%2,%3}, {%4,%5,%6,%7}, {%8,%9}, {%0,%1,%2,%3};"
                 : "+f"(c[0]), "+f"(c[1]), "+f"(c[2]), "+f"(c[3])
                 : "r"(a[0]), "r"(a[1]), "r"(a[2]), "r"(a[3]), "r"(b[0]), "r"(b[1]));
}

// ---------------- setup: zero cursors + dtype probe ----------------
__global__ void setup_kernel(const void* eptr) {
    int i = blockIdx.x * blockDim.x + threadIdx.x;
    if (i < NN) g_deg[i] = 0;
    if (blockIdx.x == 0 && threadIdx.x < 32) {
        const long long* e64 = (const long long*)eptr;
        int lane = threadIdx.x;
        bool ok = true;
#pragma unroll
        for (int q = 0; q < 8; q++) {
            long long v = e64[lane * 8 + q];
            if (v < 0 || v >= NN) ok = false;
        }
        unsigned all_ok = __all_sync(0xffffffffu, ok);
        if (lane == 0) g_is64 = all_ok ? 1 : 0;
    }
}

__device__ __forceinline__ void load_edge(const void* eptr, int e, int& row, int& col) {
    if (e >= NE) { row = col = e - NE; return; }    // self loops
    if (g_is64) {
        const long long* p = (const long long*)eptr;
        row = (int)p[e];
        col = (int)p[NE + e];
    } else {
        const int* p = (const int*)eptr;
        row = p[e];
        col = p[NE + e];
    }
}

// ---------------- one-pass padded-bucket scatter ----------------
__global__ void scatter2_kernel(const void* eptr) {
    int e = blockIdx.x * blockDim.x + threadIdx.x;
    if (e >= ET) return;
    int row, col;
    load_edge(eptr, e, row, col);
    int pos = atomicAdd(&g_deg[col], 1);
    if (pos < BUCKET) g_row2[col * BUCKET + pos] = row;   // clamp for memory safety
}

// ---------------- prep: wal = W2 @ a2_l, war = W2 @ a2_r ----------------
__global__ void prep_kernel(const float* __restrict__ W2, const float* __restrict__ attn2) {
    int k = threadIdx.x;   // 128 threads
    float sl = 0.f, sr = 0.f;
#pragma unroll 16
    for (int j = 0; j < 64; j++) {
        float w = W2[k * 64 + j];
        sl += w * attn2[j];
        sr += w * attn2[64 + j];
    }
    g_wal[k] = sl;
    g_war[k] = sr;
}

// ============ GEMM1 via HMMA:  g_h1h = fp16( fp16(x) @ fp16(W1) ) ============
__global__ __launch_bounds__(256) void gemm1_mma_kernel(const float* __restrict__ A,
                                                        const float* __restrict__ B) {
    __shared__ __align__(16) __half Ah[128][40];
    __shared__ __align__(16) __half Bh[32][136];
    int tid = threadIdx.x;
    int wid = tid >> 5, lane = tid & 31;
    int wm = wid & 3, wn = wid >> 2;
    int rowBase = blockIdx.x * 128;

    float c[2][8][4];
#pragma unroll
    for (int i = 0; i < 2; i++)
#pragma unroll
        for (int j = 0; j < 8; j++)
#pragma unroll
            for (int q = 0; q < 4; q++) c[i][j][q] = 0.f;

    for (int k0 = 0; k0 < 128; k0 += 32) {
#pragma unroll
        for (int p = 0; p < 4; p++) {
            int f = p * 256 + tid;
            int r = f >> 3, c4 = f & 7;
            int gr = rowBase + r;
            float4 v = (gr < NN) ? *reinterpret_cast<const float4*>(&A[gr * 128 + k0 + c4 * 4])
                                 : make_float4(0.f, 0.f, 0.f, 0.f);
            *reinterpret_cast<__half2*>(&Ah[r][c4 * 4])     = __floats2half2_rn(v.x, v.y);
            *reinterpret_cast<__half2*>(&Ah[r][c4 * 4 + 2]) = __floats2half2_rn(v.z, v.w);
        }
#pragma unroll
        for (int p = 0; p < 4; p++) {
            int f = p * 256 + tid;
            int r = f >> 5, c4 = f & 31;
            float4 v = *reinterpret_cast<const float4*>(&B[(k0 + r) * 128 + c4 * 4]);
            *reinterpret_cast<__half2*>(&Bh[r][c4 * 4])     = __floats2half2_rn(v.x, v.y);
            *reinterpret_cast<__half2*>(&Bh[r][c4 * 4 + 2]) = __floats2half2_rn(v.z, v.w);
        }
        __syncthreads();
#pragma unroll
        for (int ks = 0; ks < 2; ks++) {
            unsigned a[2][4];
#pragma unroll
            for (int im = 0; im < 2; im++) {
                int row = wm * 32 + im * 16 + (lane & 15);
                int col = ks * 16 + (lane >> 4) * 8;
                ldsm_x4(a[im][0], a[im][1], a[im][2], a[im][3], smaddr(&Ah[row][col]));
            }
            unsigned b[8][2];
#pragma unroll
            for (int j2 = 0; j2 < 4; j2++) {
                int krow = ks * 16 + (lane & 15);
                int col = wn * 64 + j2 * 16 + (lane >> 4) * 8;
                ldsm_x4_t(b[j2 * 2][0], b[j2 * 2][1], b[j2 * 2 + 1][0], b[j2 * 2 + 1][1],
                          smaddr(&Bh[krow][col]));
            }
#pragma unroll
            for (int im = 0; im < 2; im++)
#pragma unroll
                for (int jn = 0; jn < 8; jn++)
                    mma16816(c[im][jn], a[im], b[jn]);
        }
        __syncthreads();
    }

    int r0 = rowBase + wm * 32 + (lane >> 2);
#pragma unroll
    for (int im = 0; im < 2; im++) {
        int r = r0 + im * 16;
#pragma unroll
        for (int jn = 0; jn < 8; jn++) {
            int gc = wn * 64 + jn * 8 + 2 * (lane & 3);
            if (r < NN)
                *reinterpret_cast<__half2*>(&g_h1h[r * 128 + gc]) = __floats2half2_rn(c[im][jn][0], c[im][jn][1]);
            if (r + 8 < NN)
                *reinterpret_cast<__half2*>(&g_h1h[(r + 8) * 128 + gc]) = __floats2half2_rn(c[im][jn][2], c[im][jn][3]);
        }
    }
}

// ---------------- att1 logits (read fp16 h1) ----------------
__global__ void att1_kernel(const float* __restrict__ attn1) {
    int i = blockIdx.x * blockDim.x + threadIdx.x;   // n*4 + h
    if (i >= NN * 4) return;
    int n = i >> 2, h = i & 3;
    const __half* hp = &g_h1h[n * 128 + h * 32];
    const float* al = attn1 + h * 64;
    float s = 0.f, d = 0.f;
#pragma unroll
    for (int q = 0; q < 4; q++) {
        uint4 v = *reinterpret_cast<const uint4*>(hp + q * 8);
        const __half2* hh = reinterpret_cast<const __half2*>(&v);
#pragma unroll
        for (int t = 0; t < 4; t++) {
            float2 f = __half22float2(hh[t]);
            int j = q * 8 + t * 2;
            s += f.x * al[j] + f.y * al[j + 1];
            d += f.x * al[32 + j] + f.y * al[32 + j + 1];
        }
    }
    g_e1s[i] = s;
    g_e1d[i] = d;
}

// ============ Fused layer 2: agg1 (warp/node) -> smem tile -> HMMA gemm2 ============
// block = 256 threads (8 warps), handles 128 dst nodes.
// dynamic smem: Ah[128][136] halves (34816 B) + Bh[128][72] halves (18432 B)
__global__ __launch_bounds__(256) void layer2_fused_kernel(const float* __restrict__ W2) {
    extern __shared__ __align__(16) char dyn[];
    __half (*Ah)[136] = reinterpret_cast<__half(*)[136]>(dyn);
    __half (*Bh)[72]  = reinterpret_cast<__half(*)[72]>(dyn + 128 * 136 * 2);
    __shared__ float sw[8][128];

    int tid = threadIdx.x;
    int wid = tid >> 5, lane = tid & 31;
    int rowBase = blockIdx.x * 128;

    // convert W2 -> Bh (fp16) once; overlaps with nothing but is cheap (8 iters)
#pragma unroll
    for (int p = 0; p < 8; p++) {
        int f = p * 256 + tid;          // 2048 float4 segments of W2 (128x64 / 4... 128*16=2048)
        int r = f >> 4, c4 = f & 15;
        float4 v = *reinterpret_cast<const float4*>(&W2[r * 64 + c4 * 4]);
        *reinterpret_cast<__half2*>(&Bh[r][c4 * 4])     = __floats2half2_rn(v.x, v.y);
        *reinterpret_cast<__half2*>(&Bh[r][c4 * 4 + 2]) = __floats2half2_rn(v.z, v.w);
    }

    // phase 1: aggregation, warp w handles 16 nodes
    float* swp = sw[wid];
    int hh = lane >> 3;
    float4 wal4 = *reinterpret_cast<const float4*>(&g_wal[lane * 4]);
    float4 war4 = *reinterpret_cast<const float4*>(&g_war[lane * 4]);

    for (int t = 0; t < 16; t++) {
        int nloc = wid * 16 + t;
        int v = rowBase + nloc;
        if (v < NN) {
            int deg = min(g_deg[v], BUCKET);
            float4 ed4 = *reinterpret_cast<const float4*>(&g_e1d[v * 4]);
            float4 sum4 = {0.f, 0.f, 0.f, 0.f};
            float4 acc4 = {0.f, 0.f, 0.f, 0.f};
            for (int base = 0; base < deg; base += 32) {
                int idx = base + lane;
                int r = (idx < deg) ? g_row2[v * BUCKET + idx] : 0;
                float4 w4 = {0.f, 0.f, 0.f, 0.f};
                if (idx < deg) {
                    float4 es = *reinterpret_cast<const float4*>(&g_e1s[r * 4]);
                    w4.x = __expf(lrelu(es.x + ed4.x));
                    w4.y = __expf(lrelu(es.y + ed4.y));
                    w4.z = __expf(lrelu(es.z + ed4.z));
                    w4.w = __expf(lrelu(es.w + ed4.w));
                }
                sum4.x += w4.x; sum4.y += w4.y; sum4.z += w4.z; sum4.w += w4.w;
                reinterpret_cast<float4*>(swp)[lane] = w4;
                __syncwarp();
                int m = min(32, deg - base);
#pragma unroll 8
                for (int j = 0; j < m; j++) {
                    int rj = __shfl_sync(0xffffffffu, r, j);
                    float wj = swp[j * 4 + hh];
                    uint2 hv = *reinterpret_cast<const uint2*>(&g_h1h[rj * 128 + lane * 4]);
                    float2 f0 = __half22float2(*reinterpret_cast<half2*>(&hv.x));
                    float2 f1 = __half22float2(*reinterpret_cast<half2*>(&hv.y));
                    acc4.x += wj * f0.x;
                    acc4.y += wj * f0.y;
                    acc4.z += wj * f1.x;
                    acc4.w += wj * f1.y;
                }
                __syncwarp();
            }
#pragma unroll
            for (int o = 16; o; o >>= 1) {
                sum4.x += __shfl_xor_sync(0xffffffffu, sum4.x, o);
                sum4.y += __shfl_xor_sync(0xffffffffu, sum4.y, o);
                sum4.z += __shfl_xor_sync(0xffffffffu, sum4.z, o);
                sum4.w += __shfl_xor_sync(0xffffffffu, sum4.w, o);
            }
            float sumh = (hh == 0) ? sum4.x : (hh == 1) ? sum4.y : (hh == 2) ? sum4.z : sum4.w;
            float inv = 1.f / sumh;
            float4 o4;
            o4.x = fmaxf(acc4.x * inv, 0.f);
            o4.y = fmaxf(acc4.y * inv, 0.f);
            o4.z = fmaxf(acc4.z * inv, 0.f);
            o4.w = fmaxf(acc4.w * inv, 0.f);

            // store fp16 row into smem A tile
            __half2 h01 = __floats2half2_rn(o4.x, o4.y);
            __half2 h23 = __floats2half2_rn(o4.z, o4.w);
            uint2 hv2;
            hv2.x = *reinterpret_cast<unsigned*>(&h01);
            hv2.y = *reinterpret_cast<unsigned*>(&h23);
            *reinterpret_cast<uint2*>(&Ah[nloc][lane * 4]) = hv2;

            // e2 logits from fp32 hr:  e2s = hr . (W2@a_l)
            float es2 = o4.x * wal4.x + o4.y * wal4.y + o4.z * wal4.z + o4.w * wal4.w;
            float ed2 = o4.x * war4.x + o4.y * war4.y + o4.z * war4.z + o4.w * war4.w;
#pragma unroll
            for (int o = 16; o; o >>= 1) {
                es2 += __shfl_xor_sync(0xffffffffu, es2, o);
                ed2 += __shfl_xor_sync(0xffffffffu, ed2, o);
            }
            if (lane == 0) {
                g_e2s[v] = es2;
                g_e2d[v] = ed2;
            }
        }
    }
    __syncthreads();

    // phase 2: 128x64x128 HMMA on smem-resident A, no staging syncs
    int wm = wid & 3, wn = wid >> 2;
    float c[2][4][4];
#pragma unroll
    for (int i = 0; i < 2; i++)
#pragma unroll
        for (int j = 0; j < 4; j++)
#pragma unroll
            for (int q = 0; q < 4; q++) c[i][j][q] = 0.f;

#pragma unroll
    for (int k0 = 0; k0 < 128; k0 += 32) {
#pragma unroll
        for (int ks = 0; ks < 2; ks++) {
            unsigned a[2][4];
#pragma unroll
            for (int im = 0; im < 2; im++) {
                int row = wm * 32 + im * 16 + (lane & 15);
                int col = k0 + ks * 16 + (lane >> 4) * 8;
                ldsm_x4(a[im][0], a[im][1], a[im][2], a[im][3], smaddr(&Ah[row][col]));
            }
            unsigned b[4][2];
#pragma unroll
            for (int j2 = 0; j2 < 2; j2++) {
                int krow = k0 + ks * 16 + (lane & 15);
                int col = wn * 32 + j2 * 16 + (lane >> 4) * 8;
                ldsm_x4_t(b[j2 * 2][0], b[j2 * 2][1], b[j2 * 2 + 1][0], b[j2 * 2 + 1][1],
                          smaddr(&Bh[krow][col]));
            }
#pragma unroll
            for (int im = 0; im < 2; im++)
#pragma unroll
                for (int jn = 0; jn < 4; jn++)
                    mma16816(c[im][jn], a[im], b[jn]);
        }
    }

    int r0 = rowBase + wm * 32 + (lane >> 2);
#pragma unroll
    for (int im = 0; im < 2; im++) {
        int r = r0 + im * 16;
#pragma unroll
        for (int jn = 0; jn < 4; jn++) {
            int gc = wn * 32 + jn * 8 + 2 * (lane & 3);
            if (r < NN)
                *reinterpret_cast<__half2*>(&g_h2h[r * 64 + gc]) = __floats2half2_rn(c[im][jn][0], c[im][jn][1]);
            if (r + 8 < NN)
                *reinterpret_cast<__half2*>(&g_h2h[(r + 8) * 64 + gc]) = __floats2half2_rn(c[im][jn][2], c[im][jn][3]);
        }
    }
}

// ---------------- layer2 aggregation + output head: 1 warp / dst node ----------------
__global__ void agg2_head_kernel(const float* __restrict__ headW,
                                 const float* __restrict__ headb,
                                 float* __restrict__ out) {
    int gw = (blockIdx.x * blockDim.x + threadIdx.x) >> 5;
    if (gw >= NN) return;
    int lane = threadIdx.x & 31;
    int wib  = threadIdx.x >> 5;
    int v = gw;
    int deg = min(g_deg[v], BUCKET);
    float ed = g_e2d[v];

    float sum = 0.f;
    float2 acc = {0.f, 0.f};
    for (int base = 0; base < deg; base += 32) {
        int idx = base + lane;
        int r = (idx < deg) ? g_row2[v * BUCKET + idx] : 0;
        float w = (idx < deg) ? __expf(lrelu(g_e2s[r] + ed)) : 0.f;
        sum += w;
        int m = min(32, deg - base);
#pragma unroll 8
        for (int j = 0; j < m; j++) {
            int rj = __shfl_sync(0xffffffffu, r, j);
            float wj = __shfl_sync(0xffffffffu, w, j);
            unsigned hv = *reinterpret_cast<const unsigned*>(&g_h2h[rj * 64 + lane * 2]);
            float2 f = __half22float2(*reinterpret_cast<half2*>(&hv));
            acc.x += wj * f.x;
            acc.y += wj * f.y;
        }
    }
#pragma unroll
    for (int o = 16; o; o >>= 1) sum += __shfl_xor_sync(0xffffffffu, sum, o);
    float inv = 1.f / sum;

    __shared__ float sv[8][64];
    float* svp = sv[wib];
    svp[lane * 2]     = acc.x * inv;
    svp[lane * 2 + 1] = acc.y * inv;
    __syncwarp();

    int c = lane * 2;
    unsigned long long o2 = pack2(headb[c], headb[c + 1]);
#pragma unroll 16
    for (int k = 0; k < 64; k++) {
        float a = svp[k];
        unsigned long long aa = pack2(a, a);
        unsigned long long bb = *reinterpret_cast<const unsigned long long*>(&headW[k * 64 + c]);
        fma2(o2, aa, bb);
    }
    *reinterpret_cast<unsigned long long*>(&out[v * 64 + c]) = o2;
}

// ---------------- host orchestration ----------------
extern "C" void kernel_launch(void* const* d_in, const int* in_sizes, int n_in,
                              void* d_out, int out_size) {
    const float* x     = (const float*)d_in[0];
    const void*  eidx  = d_in[1];
    const float* W1    = (const float*)d_in[2];
    const float* attn1 = (const float*)d_in[3];
    const float* W2    = (const float*)d_in[4];
    const float* attn2 = (const float*)d_in[5];
    const float* headW = (const float*)d_in[6];
    const float* headb = (const float*)d_in[7];
    float* out = (float*)d_out;

    static cudaStream_t s2 = nullptr;
    static cudaEvent_t ev_fork = nullptr, ev_join = nullptr;
    static int smem_set = 0;
    const int DYN_SMEM = 128 * 136 * 2 + 128 * 72 * 2;   // 53248 B
    if (!s2) {
        cudaStreamCreate(&s2);
        cudaEventCreateWithFlags(&ev_fork, cudaEventDisableTiming);
        cudaEventCreateWithFlags(&ev_join, cudaEventDisableTiming);
    }
    if (!smem_set) {
        cudaFuncSetAttribute(layer2_fused_kernel, cudaFuncAttributeMaxDynamicSharedMemorySize, DYN_SMEM);
        smem_set = 1;
    }

    // fork: adjacency build + prep on s2, gemm1+att1 on capture stream
    cudaEventRecord(ev_fork, 0);
    cudaStreamWaitEvent(s2, ev_fork, 0);

    gemm1_mma_kernel<<<(NN + 127) / 128, 256>>>(x, W1);
    att1_kernel<<<(NN * 4 + 255) / 256, 256>>>(attn1);

    setup_kernel<<<(NN + 255) / 256, 256, 0, s2>>>(eidx);
    scatter2_kernel<<<(ET + 255) / 256, 256, 0, s2>>>(eidx);
    prep_kernel<<<1, 128, 0, s2>>>(W2, attn2);
    cudaEventRecord(ev_join, s2);
    cudaStreamWaitEvent(0, ev_join, 0);

    // join: fused layer-2 (agg1 + gemm2 + e2 logits), then layer-2 agg + head
    layer2_fused_kernel<<<(NN + 127) / 128, 256, DYN_SMEM>>>(W2);
    agg2_head_kernel<<<(NN + 7) / 8, 256>>>(headW, headb, out);
}

// round 10
// speedup vs baseline: 1.1097x; 1.1097x over previous
#include <cuda_runtime.h>
#include <cuda_fp16.h>

#define NN 50000
#define NE 800000
#define ET (NE + NN)
#define SLOPE 0.2f
#define BUCKET 64        // padded CSR stride; deg ~ Poisson(16)+1, P(deg>63) ~ e^-30

// ---------------- scratch (static device globals; no allocation) ----------------
__device__ __half g_h1h[NN * 128];   // layer1 projected features (fp16)
__device__ float  g_e1s[NN * 4];
__device__ float  g_e1d[NN * 4];
__device__ __half g_hrh[NN * 128];   // layer1 output post-relu (fp16, gemm2 input)
__device__ __half g_h2h[NN * 64];    // layer2 projected (fp16)
__device__ float  g_e2s[NN];
__device__ float  g_e2d[NN];
__device__ float  g_wal[128];        // W2 @ a2_l  (for e2 logits)
__device__ float  g_war[128];        // W2 @ a2_r
__device__ int    g_deg[NN];         // atomic cursors == final degrees
__device__ int    g_row2[NN * BUCKET]; // padded adjacency (by dst)
__device__ int    g_is64;

// ---------------- small helpers ----------------
__device__ __forceinline__ unsigned long long pack2(float lo, float hi) {
    unsigned long long r;
    asm("mov.b64 %0, {%1, %2};" : "=l"(r) : "f"(lo), "f"(hi));
    return r;
}
__device__ __forceinline__ void fma2(unsigned long long& d, unsigned long long a, unsigned long long b) {
    asm("fma.rn.f32x2 %0, %1, %2, %0;" : "+l"(d) : "l"(a), "l"(b));
}
__device__ __forceinline__ float lrelu(float a) { return a > 0.f ? a : SLOPE * a; }

__device__ __forceinline__ unsigned smaddr(const void* p) {
    return (unsigned)__cvta_generic_to_shared(p);
}
__device__ __forceinline__ void ldsm_x4(unsigned& r0, unsigned& r1, unsigned& r2, unsigned& r3, unsigned a) {
    asm volatile("ldmatrix.sync.aligned.m8n8.x4.shared.b16 {%0,%1,%2,%3}, [%4];"
                 : "=r"(r0), "=r"(r1), "=r"(r2), "=r"(r3) : "r"(a));
}
__device__ __forceinline__ void ldsm_x4_t(unsigned& r0, unsigned& r1, unsigned& r2, unsigned& r3, unsigned a) {
    asm volatile("ldmatrix.sync.aligned.m8n8.x4.trans.shared.b16 {%0,%1,%2,%3}, [%4];"
                 : "=r"(r0), "=r"(r1), "=r"(r2), "=r"(r3) : "r"(a));
}
__device__ __forceinline__ void mma16816(float* c, const unsigned* a, const unsigned* b) {
    asm volatile("mma.sync.aligned.m16n8k16.row.col.f32.f16.f16.f32 "
                 "{%0,%1,%2,%3}, {%4,%5,%6,%7}, {%8,%9}, {%0,%1,%2,%3};"
                 : "+f"(c[0]), "+f"(c[1]), "+f"(c[2]), "+f"(c[3])
                 : "r"(a[0]), "r"(a[1]), "r"(a[2]), "r"(a[3]), "r"(b[0]), "r"(b[1]));
}

// ---------------- setup: zero cursors + dtype probe ----------------
__global__ void setup_kernel(const void* eptr) {
    int i = blockIdx.x * blockDim.x + threadIdx.x;
    if (i < NN) g_deg[i] = 0;
    if (blockIdx.x == 0 && threadIdx.x < 32) {
        const long long* e64 = (const long long*)eptr;
        int lane = threadIdx.x;
        bool ok = true;
#pragma unroll
        for (int q = 0; q < 8; q++) {
            long long v = e64[lane * 8 + q];
            if (v < 0 || v >= NN) ok = false;
        }
        unsigned all_ok = __all_sync(0xffffffffu, ok);
        if (lane == 0) g_is64 = all_ok ? 1 : 0;
    }
}

// ---------------- one-pass padded-bucket scatter, 4 edges/thread (MLP) ----------------
__global__ void scatter2_kernel(const void* eptr) {
    int base = (blockIdx.x * blockDim.x + threadIdx.x) * 4;
    if (base >= ET) return;
    int rows[4], cols[4];
    if (g_is64) {
        const long long* p = (const long long*)eptr;
#pragma unroll
        for (int q = 0; q < 4; q++) {
            int e = base + q;
            if (e < ET) {
                if (e >= NE) { rows[q] = cols[q] = e - NE; }
                else { rows[q] = (int)p[e]; cols[q] = (int)p[NE + e]; }
            }
        }
    } else {
        const int* p = (const int*)eptr;
#pragma unroll
        for (int q = 0; q < 4; q++) {
            int e = base + q;
            if (e < ET) {
                if (e >= NE) { rows[q] = cols[q] = e - NE; }
                else { rows[q] = p[e]; cols[q] = p[NE + e]; }
            }
        }
    }
#pragma unroll
    for (int q = 0; q < 4; q++) {
        int e = base + q;
        if (e < ET) {
            int pos = atomicAdd(&g_deg[cols[q]], 1);
            if (pos < BUCKET) g_row2[cols[q] * BUCKET + pos] = rows[q];
        }
    }
}

// ---------------- prep: wal = W2 @ a2_l, war = W2 @ a2_r ----------------
__global__ void prep_kernel(const float* __restrict__ W2, const float* __restrict__ attn2) {
    int k = threadIdx.x;   // 128 threads
    float sl = 0.f, sr = 0.f;
#pragma unroll 16
    for (int j = 0; j < 64; j++) {
        float w = W2[k * 64 + j];
        sl += w * attn2[j];
        sr += w * attn2[64 + j];
    }
    g_wal[k] = sl;
    g_war[k] = sr;
}

// ============ GEMM1 via HMMA:  g_h1h = fp16( fp16(x) @ fp16(W1) ) ============
__global__ __launch_bounds__(256) void gemm1_mma_kernel(const float* __restrict__ A,
                                                        const float* __restrict__ B) {
    __shared__ __align__(16) __half Ah[128][40];
    __shared__ __align__(16) __half Bh[32][136];
    int tid = threadIdx.x;
    int wid = tid >> 5, lane = tid & 31;
    int wm = wid & 3, wn = wid >> 2;
    int rowBase = blockIdx.x * 128;

    float c[2][8][4];
#pragma unroll
    for (int i = 0; i < 2; i++)
#pragma unroll
        for (int j = 0; j < 8; j++)
#pragma unroll
            for (int q = 0; q < 4; q++) c[i][j][q] = 0.f;

    for (int k0 = 0; k0 < 128; k0 += 32) {
#pragma unroll
        for (int p = 0; p < 4; p++) {
            int f = p * 256 + tid;
            int r = f >> 3, c4 = f & 7;
            int gr = rowBase + r;
            float4 v = (gr < NN) ? *reinterpret_cast<const float4*>(&A[gr * 128 + k0 + c4 * 4])
                                 : make_float4(0.f, 0.f, 0.f, 0.f);
            *reinterpret_cast<__half2*>(&Ah[r][c4 * 4])     = __floats2half2_rn(v.x, v.y);
            *reinterpret_cast<__half2*>(&Ah[r][c4 * 4 + 2]) = __floats2half2_rn(v.z, v.w);
        }
#pragma unroll
        for (int p = 0; p < 4; p++) {
            int f = p * 256 + tid;
            int r = f >> 5, c4 = f & 31;
            float4 v = *reinterpret_cast<const float4*>(&B[(k0 + r) * 128 + c4 * 4]);
            *reinterpret_cast<__half2*>(&Bh[r][c4 * 4])     = __floats2half2_rn(v.x, v.y);
            *reinterpret_cast<__half2*>(&Bh[r][c4 * 4 + 2]) = __floats2half2_rn(v.z, v.w);
        }
        __syncthreads();
#pragma unroll
        for (int ks = 0; ks < 2; ks++) {
            unsigned a[2][4];
#pragma unroll
            for (int im = 0; im < 2; im++) {
                int row = wm * 32 + im * 16 + (lane & 15);
                int col = ks * 16 + (lane >> 4) * 8;
                ldsm_x4(a[im][0], a[im][1], a[im][2], a[im][3], smaddr(&Ah[row][col]));
            }
            unsigned b[8][2];
#pragma unroll
            for (int j2 = 0; j2 < 4; j2++) {
                int krow = ks * 16 + (lane & 15);
                int col = wn * 64 + j2 * 16 + (lane >> 4) * 8;
                ldsm_x4_t(b[j2 * 2][0], b[j2 * 2][1], b[j2 * 2 + 1][0], b[j2 * 2 + 1][1],
                          smaddr(&Bh[krow][col]));
            }
#pragma unroll
            for (int im = 0; im < 2; im++)
#pragma unroll
                for (int jn = 0; jn < 8; jn++)
                    mma16816(c[im][jn], a[im], b[jn]);
        }
        __syncthreads();
    }

    int r0 = rowBase + wm * 32 + (lane >> 2);
#pragma unroll
    for (int im = 0; im < 2; im++) {
        int r = r0 + im * 16;
#pragma unroll
        for (int jn = 0; jn < 8; jn++) {
            int gc = wn * 64 + jn * 8 + 2 * (lane & 3);
            if (r < NN)
                *reinterpret_cast<__half2*>(&g_h1h[r * 128 + gc]) = __floats2half2_rn(c[im][jn][0], c[im][jn][1]);
            if (r + 8 < NN)
                *reinterpret_cast<__half2*>(&g_h1h[(r + 8) * 128 + gc]) = __floats2half2_rn(c[im][jn][2], c[im][jn][3]);
        }
    }
}

// ============ GEMM2 via HMMA: g_h2h = fp16( g_hrh @ fp16(W2) ) ============
__global__ __launch_bounds__(256) void gemm2_mma_kernel(const float* __restrict__ B) {
    __shared__ __align__(16) __half Ah[128][40];
    __shared__ __align__(16) __half Bh[32][72];
    int tid = threadIdx.x;
    int wid = tid >> 5, lane = tid & 31;
    int wm = wid & 3, wn = wid >> 2;
    int rowBase = blockIdx.x * 128;

    float c[2][4][4];
#pragma unroll
    for (int i = 0; i < 2; i++)
#pragma unroll
        for (int j = 0; j < 4; j++)
#pragma unroll
            for (int q = 0; q < 4; q++) c[i][j][q] = 0.f;

    for (int k0 = 0; k0 < 128; k0 += 32) {
#pragma unroll
        for (int p = 0; p < 2; p++) {
            int u = p * 256 + tid;
            int r = u >> 2, c8 = u & 3;
            int gr = rowBase + r;
            uint4 v = (gr < NN) ? *reinterpret_cast<const uint4*>(&g_hrh[gr * 128 + k0 + c8 * 8])
                                : make_uint4(0u, 0u, 0u, 0u);
            *reinterpret_cast<uint4*>(&Ah[r][c8 * 8]) = v;
        }
#pragma unroll
        for (int p = 0; p < 2; p++) {
            int f = p * 256 + tid;
            int r = f >> 4, c4 = f & 15;
            float4 v = *reinterpret_cast<const float4*>(&B[(k0 + r) * 64 + c4 * 4]);
            *reinterpret_cast<__half2*>(&Bh[r][c4 * 4])     = __floats2half2_rn(v.x, v.y);
            *reinterpret_cast<__half2*>(&Bh[r][c4 * 4 + 2]) = __floats2half2_rn(v.z, v.w);
        }
        __syncthreads();
#pragma unroll
        for (int ks = 0; ks < 2; ks++) {
            unsigned a[2][4];
#pragma unroll
            for (int im = 0; im < 2; im++) {
                int row = wm * 32 + im * 16 + (lane & 15);
                int col = ks * 16 + (lane >> 4) * 8;
                ldsm_x4(a[im][0], a[im][1], a[im][2], a[im][3], smaddr(&Ah[row][col]));
            }
            unsigned b[4][2];
#pragma unroll
            for (int j2 = 0; j2 < 2; j2++) {
                int krow = ks * 16 + (lane & 15);
                int col = wn * 32 + j2 * 16 + (lane >> 4) * 8;
                ldsm_x4_t(b[j2 * 2][0], b[j2 * 2][1], b[j2 * 2 + 1][0], b[j2 * 2 + 1][1],
                          smaddr(&Bh[krow][col]));
            }
#pragma unroll
            for (int im = 0; im < 2; im++)
#pragma unroll
                for (int jn = 0; jn < 4; jn++)
                    mma16816(c[im][jn], a[im], b[jn]);
        }
        __syncthreads();
    }

    int r0 = rowBase + wm * 32 + (lane >> 2);
#pragma unroll
    for (int im = 0; im < 2; im++) {
        int r = r0 + im * 16;
#pragma unroll
        for (int jn = 0; jn < 4; jn++) {
            int gc = wn * 32 + jn * 8 + 2 * (lane & 3);
            if (r < NN)
                *reinterpret_cast<__half2*>(&g_h2h[r * 64 + gc]) = __floats2half2_rn(c[im][jn][0], c[im][jn][1]);
            if (r + 8 < NN)
                *reinterpret_cast<__half2*>(&g_h2h[(r + 8) * 64 + gc]) = __floats2half2_rn(c[im][jn][2], c[im][jn][3]);
        }
    }
}

// ---------------- att1 logits (read fp16 h1) ----------------
__global__ void att1_kernel(const float* __restrict__ attn1) {
    int i = blockIdx.x * blockDim.x + threadIdx.x;   // n*4 + h
    if (i >= NN * 4) return;
    int n = i >> 2, h = i & 3;
    const __half* hp = &g_h1h[n * 128 + h * 32];
    const float* al = attn1 + h * 64;
    float s = 0.f, d = 0.f;
#pragma unroll
    for (int q = 0; q < 4; q++) {
        uint4 v = *reinterpret_cast<const uint4*>(hp + q * 8);
        const __half2* hh = reinterpret_cast<const __half2*>(&v);
#pragma unroll
        for (int t = 0; t < 4; t++) {
            float2 f = __half22float2(hh[t]);
            int j = q * 8 + t * 2;
            s += f.x * al[j] + f.y * al[j + 1];
            d += f.x * al[32 + j] + f.y * al[32 + j + 1];
        }
    }
    g_e1s[i] = s;
    g_e1d[i] = d;
}

// ---------------- layer1 aggregation: 1 warp / dst node; e2 logits in epilogue ----------
__global__ void agg1_kernel() {
    int gw = (blockIdx.x * blockDim.x + threadIdx.x) >> 5;
    if (gw >= NN) return;
    int lane = threadIdx.x & 31;
    int wib  = threadIdx.x >> 5;
    int v = gw;
    int deg = min(g_deg[v], BUCKET);
    float4 ed4 = *reinterpret_cast<const float4*>(&g_e1d[v * 4]);
    int hh = lane >> 3;

    __shared__ float sw[8][128];
    float* swp = sw[wib];

    float4 sum4 = {0.f, 0.f, 0.f, 0.f};
    float4 acc4 = {0.f, 0.f, 0.f, 0.f};

    for (int base = 0; base < deg; base += 32) {
        int idx = base + lane;
        int r = (idx < deg) ? g_row2[v * BUCKET + idx] : 0;
        float4 w4 = {0.f, 0.f, 0.f, 0.f};
        if (idx < deg) {
            float4 es = *reinterpret_cast<const float4*>(&g_e1s[r * 4]);
            w4.x = __expf(lrelu(es.x + ed4.x));
            w4.y = __expf(lrelu(es.y + ed4.y));
            w4.z = __expf(lrelu(es.z + ed4.z));
            w4.w = __expf(lrelu(es.w + ed4.w));
        }
        sum4.x += w4.x; sum4.y += w4.y; sum4.z += w4.z; sum4.w += w4.w;
        reinterpret_cast<float4*>(swp)[lane] = w4;
        __syncwarp();
        int m = min(32, deg - base);
#pragma unroll 8
        for (int j = 0; j < m; j++) {
            int rj = __shfl_sync(0xffffffffu, r, j);
            float wj = swp[j * 4 + hh];
            uint2 hv = *reinterpret_cast<const uint2*>(&g_h1h[rj * 128 + lane * 4]);
            float2 f0 = __half22float2(*reinterpret_cast<half2*>(&hv.x));
            float2 f1 = __half22float2(*reinterpret_cast<half2*>(&hv.y));
            acc4.x += wj * f0.x;
            acc4.y += wj * f0.y;
            acc4.z += wj * f1.x;
            acc4.w += wj * f1.y;
        }
        __syncwarp();
    }
#pragma unroll
    for (int o = 16; o; o >>= 1) {
        sum4.x += __shfl_xor_sync(0xffffffffu, sum4.x, o);
        sum4.y += __shfl_xor_sync(0xffffffffu, sum4.y, o);
        sum4.z += __shfl_xor_sync(0xffffffffu, sum4.z, o);
        sum4.w += __shfl_xor_sync(0xffffffffu, sum4.w, o);
    }
    float sumh = (hh == 0) ? sum4.x : (hh == 1) ? sum4.y : (hh == 2) ? sum4.z : sum4.w;
    float inv = 1.f / sumh;
    float4 o4;
    o4.x = fmaxf(acc4.x * inv, 0.f);
    o4.y = fmaxf(acc4.y * inv, 0.f);
    o4.z = fmaxf(acc4.z * inv, 0.f);
    o4.w = fmaxf(acc4.w * inv, 0.f);

    // store fp16 hr
    __half2 o01 = __floats2half2_rn(o4.x, o4.y);
    __half2 o23 = __floats2half2_rn(o4.z, o4.w);
    uint2 ov;
    ov.x = *reinterpret_cast<unsigned*>(&o01);
    ov.y = *reinterpret_cast<unsigned*>(&o23);
    *reinterpret_cast<uint2*>(&g_hrh[v * 128 + lane * 4]) = ov;

    // e2 logits from fp32 hr:  e2s = hr . (W2@a2_l), e2d = hr . (W2@a2_r)
    float4 wal4 = *reinterpret_cast<const float4*>(&g_wal[lane * 4]);
    float4 war4 = *reinterpret_cast<const float4*>(&g_war[lane * 4]);
    float es2 = o4.x * wal4.x + o4.y * wal4.y + o4.z * wal4.z + o4.w * wal4.w;
    float ed2 = o4.x * war4.x + o4.y * war4.y + o4.z * war4.z + o4.w * war4.w;
#pragma unroll
    for (int o = 16; o; o >>= 1) {
        es2 += __shfl_xor_sync(0xffffffffu, es2, o);
        ed2 += __shfl_xor_sync(0xffffffffu, ed2, o);
    }
    if (lane == 0) {
        g_e2s[v] = es2;
        g_e2d[v] = ed2;
    }
}

// ---------------- layer2 aggregation + output head: 1 warp / dst node ----------------
__global__ void agg2_head_kernel(const float* __restrict__ headW,
                                 const float* __restrict__ headb,
                                 float* __restrict__ out) {
    int gw = (blockIdx.x * blockDim.x + threadIdx.x) >> 5;
    if (gw >= NN) return;
    int lane = threadIdx.x & 31;
    int wib  = threadIdx.x >> 5;
    int v = gw;
    int deg = min(g_deg[v], BUCKET);
    float ed = g_e2d[v];

    float sum = 0.f;
    float2 acc = {0.f, 0.f};
    for (int base = 0; base < deg; base += 32) {
        int idx = base + lane;
        int r = (idx < deg) ? g_row2[v * BUCKET + idx] : 0;
        float w = (idx < deg) ? __expf(lrelu(g_e2s[r] + ed)) : 0.f;
        sum += w;
        int m = min(32, deg - base);
#pragma unroll 8
        for (int j = 0; j < m; j++) {
            int rj = __shfl_sync(0xffffffffu, r, j);
            float wj = __shfl_sync(0xffffffffu, w, j);
            unsigned hv = *reinterpret_cast<const unsigned*>(&g_h2h[rj * 64 + lane * 2]);
            float2 f = __half22float2(*reinterpret_cast<half2*>(&hv));
            acc.x += wj * f.x;
            acc.y += wj * f.y;
        }
    }
#pragma unroll
    for (int o = 16; o; o >>= 1) sum += __shfl_xor_sync(0xffffffffu, sum, o);
    float inv = 1.f / sum;

    __shared__ float sv[8][64];
    float* svp = sv[wib];
    svp[lane * 2]     = acc.x * inv;
    svp[lane * 2 + 1] = acc.y * inv;
    __syncwarp();

    int c = lane * 2;
    unsigned long long o2 = pack2(headb[c], headb[c + 1]);
#pragma unroll 16
    for (int k = 0; k < 64; k++) {
        float a = svp[k];
        unsigned long long aa = pack2(a, a);
        unsigned long long bb = *reinterpret_cast<const unsigned long long*>(&headW[k * 64 + c]);
        fma2(o2, aa, bb);
    }
    *reinterpret_cast<unsigned long long*>(&out[v * 64 + c]) = o2;
}

// ---------------- host orchestration ----------------
extern "C" void kernel_launch(void* const* d_in, const int* in_sizes, int n_in,
                              void* d_out, int out_size) {
    const float* x     = (const float*)d_in[0];
    const void*  eidx  = d_in[1];
    const float* W1    = (const float*)d_in[2];
    const float* attn1 = (const float*)d_in[3];
    const float* W2    = (const float*)d_in[4];
    const float* attn2 = (const float*)d_in[5];
    const float* headW = (const float*)d_in[6];
    const float* headb = (const float*)d_in[7];
    float* out = (float*)d_out;

    static cudaStream_t s2 = nullptr;
    static cudaEvent_t ev_fork = nullptr, ev_join = nullptr;
    if (!s2) {
        cudaStreamCreate(&s2);
        cudaEventCreateWithFlags(&ev_fork, cudaEventDisableTiming);
        cudaEventCreateWithFlags(&ev_join, cudaEventDisableTiming);
    }

    // fork: adjacency build + prep on s2, gemm1+att1 on capture stream
    cudaEventRecord(ev_fork, 0);
    cudaStreamWaitEvent(s2, ev_fork, 0);

    gemm1_mma_kernel<<<(NN + 127) / 128, 256>>>(x, W1);
    att1_kernel<<<(NN * 4 + 255) / 256, 256>>>(attn1);

    setup_kernel<<<(NN + 255) / 256, 256, 0, s2>>>(eidx);
    scatter2_kernel<<<(ET / 4 + 255) / 256, 256, 0, s2>>>(eidx);
    prep_kernel<<<1, 128, 0, s2>>>(W2, attn2);
    cudaEventRecord(ev_join, s2);
    cudaStreamWaitEvent(0, ev_join, 0);

    // join: agg1 (+e2 logits) -> gemm2 -> agg2+head
    agg1_kernel<<<(NN + 7) / 8, 256>>>();
    gemm2_mma_kernel<<<(NN + 127) / 128, 256>>>(W2);
    agg2_head_kernel<<<(NN + 7) / 8, 256>>>(headW, headb, out);
}